// round 2
// baseline (speedup 1.0000x reference)
#include <cuda_runtime.h>
#include <cuda_bf16.h>
#include <cstdint>

// Problem constants
#define BATCH 4
#define SEQ   2048
#define DM    1024
#define NH    16
#define HD    64
#define MROWS (BATCH*SEQ)          // 8192
#define NEGBIAS (-10000.0f)

// Scratch: head-split projections + context (no allocation allowed)
__device__ float g_qh[BATCH*NH*SEQ*HD];   // [b,h,t,hd]
__device__ float g_kh[BATCH*NH*SEQ*HD];
__device__ float g_vh[BATCH*NH*SEQ*HD];
__device__ float g_ctx[MROWS*DM];         // [b*T+t, d]

// ---------------------------------------------------------------------------
// GEMM:  out[m,n] = sum_k X[m,k] * W[n,k]     (X: [M,1024], W: [1024,1024])
// headsplit=1 -> write to [b,h,t,hd] layout; else [m, n] row-major.
// 128x128 tile, BK=16, 256 threads, 8x8 per thread.
// ---------------------------------------------------------------------------
__global__ void __launch_bounds__(256)
gemm_xwT(const float* __restrict__ X, const float* __restrict__ W,
         float* __restrict__ out, int headsplit)
{
    __shared__ float As[16][128];
    __shared__ float Bs[16][128];

    const int t  = threadIdx.x;
    const int tx = t & 15;          // 0..15  -> n sub-block
    const int ty = t >> 4;          // 0..15  -> m sub-block
    const int m0 = blockIdx.y * 128;
    const int n0 = blockIdx.x * 128;

    float acc[8][8];
#pragma unroll
    for (int i = 0; i < 8; i++)
#pragma unroll
        for (int j = 0; j < 8; j++) acc[i][j] = 0.0f;

    for (int k0 = 0; k0 < DM; k0 += 16) {
        // load tiles: 512 float4 per matrix, 2 per thread
#pragma unroll
        for (int i = 0; i < 2; i++) {
            int f4  = t + 256*i;            // 0..511
            int row = f4 >> 2;              // 0..127
            int c4  = (f4 & 3) * 4;         // 0,4,8,12
            float4 a = *(const float4*)&X[(size_t)(m0+row)*DM + k0 + c4];
            As[c4+0][row] = a.x; As[c4+1][row] = a.y;
            As[c4+2][row] = a.z; As[c4+3][row] = a.w;
            float4 b = *(const float4*)&W[(size_t)(n0+row)*DM + k0 + c4];
            Bs[c4+0][row] = b.x; Bs[c4+1][row] = b.y;
            Bs[c4+2][row] = b.z; Bs[c4+3][row] = b.w;
        }
        __syncthreads();

#pragma unroll
        for (int k = 0; k < 16; k++) {
            float af[8], bf[8];
            *(float4*)&af[0] = *(const float4*)&As[k][ty*8];
            *(float4*)&af[4] = *(const float4*)&As[k][ty*8+4];
            *(float4*)&bf[0] = *(const float4*)&Bs[k][tx*8];
            *(float4*)&bf[4] = *(const float4*)&Bs[k][tx*8+4];
#pragma unroll
            for (int i = 0; i < 8; i++)
#pragma unroll
                for (int j = 0; j < 8; j++)
                    acc[i][j] += af[i] * bf[j];
        }
        __syncthreads();
    }

    const int nb = n0 + tx*8;
#pragma unroll
    for (int i = 0; i < 8; i++) {
        int m = m0 + ty*8 + i;
        float* dst;
        if (headsplit) {
            int bb = m >> 11;       // m / SEQ
            int tt = m & 2047;      // m % SEQ
            int h  = nb >> 6;
            int dh = nb & 63;
            dst = &out[((((size_t)bb*NH + h)*SEQ) + tt)*HD + dh];
        } else {
            dst = &out[(size_t)m*DM + nb];
        }
        float4 o0 = make_float4(acc[i][0], acc[i][1], acc[i][2], acc[i][3]);
        float4 o1 = make_float4(acc[i][4], acc[i][5], acc[i][6], acc[i][7]);
        *(float4*)&dst[0] = o0;
        *(float4*)&dst[4] = o1;
    }
}

// ---------------------------------------------------------------------------
// Flash attention (fp32). One CTA = (b,h) x 128 q-rows. 128 threads,
// one q-row per thread. K tile (64 keys) stored TRANSPOSED in smem so the
// score loop is scalar-LDS(q) + broadcast LDS.128(K^T) + FFMA.
// Probabilities staged through smem so the PV loop keeps runtime j.
// ---------------------------------------------------------------------------
#define QT 128
#define KT 64
#define QPAD 65
// floats: Qs 128*65, Ss 128*65, Kst 64*64, Vs 64*64, Ps 64
#define ATTN_SMEM_FLOATS (QT*QPAD + QT*QPAD + KT*HD + KT*HD + KT)
#define ATTN_SMEM_BYTES  (ATTN_SMEM_FLOATS*4)

__global__ void __launch_bounds__(128)
attn_kernel(const float* __restrict__ qh, const float* __restrict__ kh,
            const float* __restrict__ vh, const float* __restrict__ amask,
            const int* __restrict__ mask_future, float* __restrict__ ctx)
{
    extern __shared__ float sm[];
    float* Qs  = sm;                         // [128][65]
    float* Ss  = Qs  + QT*QPAD;              // [128][65]
    float* Kst = Ss  + QT*QPAD;              // [64][64]  (Kst[k][j])
    float* Vs  = Kst + KT*HD;                // [64][64]  (Vs[j][k])
    float* Ps  = Vs  + KT*HD;                // [64]

    const int bh = blockIdx.y;               // b*NH + h
    const int b  = bh >> 4;
    const int h  = bh & 15;
    const int qt = blockIdx.x;
    const int t  = threadIdx.x;
    const int gq = qt*QT + t;                // this thread's query row (in-batch)

    const float* Qbase = qh + (size_t)bh * SEQ * HD;
    const float* Kbase = kh + (size_t)bh * SEQ * HD;
    const float* Vbase = vh + (size_t)bh * SEQ * HD;

    // load Q tile into smem (coalesced), pad-65 rows
#pragma unroll
    for (int i = 0; i < 16; i++) {
        int f4  = t + 128*i;                 // 0..2047
        int row = f4 >> 4;
        int c4  = (f4 & 15) * 4;
        float4 v = *(const float4*)&Qbase[(size_t)(qt*QT + row)*HD + c4];
        Qs[row*QPAD + c4 + 0] = v.x;
        Qs[row*QPAD + c4 + 1] = v.y;
        Qs[row*QPAD + c4 + 2] = v.z;
        Qs[row*QPAD + c4 + 3] = v.w;
    }

    const int causal = mask_future[0] != 0;
    const int kmax   = causal ? (qt*QT + QT) : SEQ;
    const int ntiles = kmax / KT;

    float m = -1e30f, l = 0.0f;
    float acc[HD];
#pragma unroll
    for (int k = 0; k < HD; k++) acc[k] = 0.0f;

    for (int kt = 0; kt < ntiles; kt++) {
        __syncthreads();
        // load K (transposed) and V tiles
        const float* Kb = Kbase + (size_t)(kt*KT)*HD;
        const float* Vb = Vbase + (size_t)(kt*KT)*HD;
#pragma unroll
        for (int i = 0; i < 8; i++) {
            int f4  = t + 128*i;             // 0..1023
            int row = f4 >> 4;               // key j: 0..63
            int c4  = (f4 & 15) * 4;         // dim k
            float4 kv = *(const float4*)&Kb[(size_t)row*HD + c4];
            Kst[(c4+0)*KT + row] = kv.x;
            Kst[(c4+1)*KT + row] = kv.y;
            Kst[(c4+2)*KT + row] = kv.z;
            Kst[(c4+3)*KT + row] = kv.w;
            float4 vv = *(const float4*)&Vb[(size_t)row*HD + c4];
            *(float4*)&Vs[row*HD + c4] = vv;
        }
        if (t < KT) Ps[t] = amask[(size_t)b*SEQ + kt*KT + t];
        __syncthreads();

        // S = (Q . K^T) : k outer, j inner (K^T rows broadcast)
        float s[KT];
#pragma unroll
        for (int j = 0; j < KT; j++) s[j] = 0.0f;
#pragma unroll 4
        for (int k = 0; k < HD; k++) {
            float qv = Qs[t*QPAD + k];
            const float4* Kr = (const float4*)&Kst[k*KT];
#pragma unroll
            for (int j4 = 0; j4 < 16; j4++) {
                float4 kk = Kr[j4];
                s[j4*4+0] += qv * kk.x;
                s[j4*4+1] += qv * kk.y;
                s[j4*4+2] += qv * kk.z;
                s[j4*4+3] += qv * kk.w;
            }
        }

        // mask + online softmax
        float tmax = -1e30f;
#pragma unroll
        for (int j = 0; j < KT; j++) {
            float sv = s[j] * 0.125f;        // 1/sqrt(64)
            int gk = kt*KT + j;
            if (causal && gk > gq) sv += NEGBIAS;
            if (Ps[j] == 0.0f) sv = NEGBIAS;
            s[j] = sv;
            tmax = fmaxf(tmax, sv);
        }
        float mn   = fmaxf(m, tmax);
        float corr = __expf(m - mn);
        l *= corr;
#pragma unroll
        for (int j = 0; j < KT; j++) {
            float p = __expf(s[j] - mn);
            l += p;
            Ss[t*QPAD + j] = p;
        }
        m = mn;
#pragma unroll
        for (int k = 0; k < HD; k++) acc[k] *= corr;

        // acc += P . V   (V rows broadcast)
#pragma unroll 2
        for (int j = 0; j < KT; j++) {
            float p = Ss[t*QPAD + j];
            const float4* Vr = (const float4*)&Vs[j*HD];
#pragma unroll
            for (int k4 = 0; k4 < 16; k4++) {
                float4 vv = Vr[k4];
                acc[k4*4+0] += p * vv.x;
                acc[k4*4+1] += p * vv.y;
                acc[k4*4+2] += p * vv.z;
                acc[k4*4+3] += p * vv.w;
            }
        }
    }

    // write context: ctx[(b*T+gq)*DM + h*HD + k]
    float rl = 1.0f / l;
    float* Cb = g_ctx + ((size_t)b*SEQ + gq)*DM + h*HD;
#pragma unroll
    for (int k4 = 0; k4 < 16; k4++) {
        float4 o;
        o.x = acc[k4*4+0] * rl;
        o.y = acc[k4*4+1] * rl;
        o.z = acc[k4*4+2] * rl;
        o.w = acc[k4*4+3] * rl;
        *(float4*)&Cb[k4*4] = o;
    }
}

// ---------------------------------------------------------------------------
extern "C" void kernel_launch(void* const* d_in, const int* in_sizes, int n_in,
                              void* d_out, int out_size)
{
    const float* q  = (const float*)d_in[0];
    const float* k  = (const float*)d_in[1];
    const float* v  = (const float*)d_in[2];
    const float* am = (const float*)d_in[3];
    const float* Wq = (const float*)d_in[4];
    const float* Wk = (const float*)d_in[5];
    const float* Wv = (const float*)d_in[6];
    const float* Wo = (const float*)d_in[7];
    const int*   mf = (const int*)  d_in[8];
    float* out = (float*)d_out;

    float *qh, *kh, *vh, *ctx;
    cudaGetSymbolAddress((void**)&qh,  g_qh);
    cudaGetSymbolAddress((void**)&kh,  g_kh);
    cudaGetSymbolAddress((void**)&vh,  g_vh);
    cudaGetSymbolAddress((void**)&ctx, g_ctx);

    static bool attr_set = false;
    if (!attr_set) {
        cudaFuncSetAttribute(attn_kernel,
                             cudaFuncAttributeMaxDynamicSharedMemorySize,
                             ATTN_SMEM_BYTES);
        attr_set = true;
    }

    dim3 ggrid(DM/128, MROWS/128);   // (8, 64)
    gemm_xwT<<<ggrid, 256>>>(q, Wq, qh, 1);
    gemm_xwT<<<ggrid, 256>>>(k, Wk, kh, 1);
    gemm_xwT<<<ggrid, 256>>>(v, Wv, vh, 1);

    dim3 agrid(SEQ/QT, BATCH*NH);    // (16, 64)
    attn_kernel<<<agrid, 128, ATTN_SMEM_BYTES>>>(qh, kh, vh, am, mf, ctx);

    gemm_xwT<<<ggrid, 256>>>(ctx, Wo, out, 0);
}

// round 4
// speedup vs baseline: 1.2860x; 1.2860x over previous
#include <cuda_runtime.h>
#include <cuda_bf16.h>
#include <cstdint>

// Problem constants
#define BATCH 4
#define SEQ   2048
#define DM    1024
#define NH    16
#define HD    64
#define MROWS (BATCH*SEQ)          // 8192
#define NEGBIAS (-10000.0f)

// Scratch (no allocation allowed)
__device__ float g_qh[BATCH*NH*SEQ*HD];   // [b,h,t,hd]
__device__ float g_kh[BATCH*NH*SEQ*HD];
__device__ float g_vh[BATCH*NH*SEQ*HD];
__device__ float g_ctx[MROWS*DM];         // [b*T+t, d]
// hi/lo bf16 split buffers (activation reused across the 4 GEMMs; weight too)
__device__ __nv_bfloat16 g_ahi[MROWS*DM];
__device__ __nv_bfloat16 g_alo[MROWS*DM];
__device__ __nv_bfloat16 g_whi[DM*DM];
__device__ __nv_bfloat16 g_wlo[DM*DM];

// ---------------------------------------------------------------------------
// helpers
// ---------------------------------------------------------------------------
__device__ __forceinline__ uint32_t smem_u32(const void* p) {
    uint32_t a;
    asm("{ .reg .u64 t; cvta.to.shared.u64 t, %1; cvt.u32.u64 %0, t; }" : "=r"(a) : "l"(p));
    return a;
}
#define SWZ128(o) ((uint32_t)(o) ^ ((((uint32_t)(o)) >> 3) & 0x70))

#define CP_ASYNC16(saddr, gptr) \
    asm volatile("cp.async.cg.shared.global [%0], [%1], 16;" :: "r"(saddr), "l"(gptr) : "memory")
#define CP_COMMIT() asm volatile("cp.async.commit_group;" ::: "memory")
#define CP_WAIT1()  asm volatile("cp.async.wait_group 1;" ::: "memory")
#define CP_WAIT0()  asm volatile("cp.async.wait_group 0;" ::: "memory")

#define LDSM4(R0,R1,R2,R3,ADDR) \
    asm volatile("ldmatrix.sync.aligned.m8n8.x4.shared.b16 {%0,%1,%2,%3}, [%4];" \
        : "=r"(R0), "=r"(R1), "=r"(R2), "=r"(R3) : "r"(ADDR))

__device__ __forceinline__ void mma16816(float* c, const uint32_t* a,
                                         uint32_t b0, uint32_t b1) {
    asm volatile(
        "mma.sync.aligned.m16n8k16.row.col.f32.bf16.bf16.f32 "
        "{%0,%1,%2,%3}, {%4,%5,%6,%7}, {%8,%9}, {%0,%1,%2,%3};"
        : "+f"(c[0]), "+f"(c[1]), "+f"(c[2]), "+f"(c[3])
        : "r"(a[0]), "r"(a[1]), "r"(a[2]), "r"(a[3]), "r"(b0), "r"(b1));
}

// ---------------------------------------------------------------------------
// split kernel: fp32 -> bf16 hi + bf16 residual lo
// ---------------------------------------------------------------------------
__global__ void __launch_bounds__(256)
split_bf16(const float4* __restrict__ src, uint2* __restrict__ hi,
           uint2* __restrict__ lo, int n4)
{
    int i = blockIdx.x * 256 + threadIdx.x;
    if (i >= n4) return;
    float4 v = src[i];
    float f[4] = {v.x, v.y, v.z, v.w};
    uint32_t h[4], l[4];
#pragma unroll
    for (int j = 0; j < 4; j++) {
        __nv_bfloat16 bh = __float2bfloat16(f[j]);
        float r = f[j] - __bfloat162float(bh);
        __nv_bfloat16 bl = __float2bfloat16(r);
        h[j] = __bfloat16_as_ushort(bh);
        l[j] = __bfloat16_as_ushort(bl);
    }
    hi[i] = make_uint2(h[0] | (h[1] << 16), h[2] | (h[3] << 16));
    lo[i] = make_uint2(l[0] | (l[1] << 16), l[2] | (l[3] << 16));
}

// ---------------------------------------------------------------------------
// HMMA GEMM: out[m,n] = sum_k X[m,k]*W[n,k], X/W pre-split bf16 hi/lo.
// CTA 128x128, BK=64, 8 warps (4 m x 2 n), warp tile 32x64,
// mma.sync m16n8k16, 3-product split, 2-stage cp.async pipeline.
// smem: stage s at s*64KB: Ahi|Alo|Bhi|Blo, each 128x64 bf16 SW128 = 16KB.
// ---------------------------------------------------------------------------
#define GT_TILE  16384
#define GT_STAGE (4*GT_TILE)
#define GSMEM_BYTES (2*GT_STAGE)   // 128 KB
#define NCHUNK 16                  // K=1024 / 64

__device__ __forceinline__ void g_load_stage(
    uint32_t sb, int stage,
    const __nv_bfloat16* __restrict__ Ahi, const __nv_bfloat16* __restrict__ Alo,
    const __nv_bfloat16* __restrict__ Bhi, const __nv_bfloat16* __restrict__ Blo,
    int m0, int n0, int k0, int t)
{
    const uint32_t base = sb + stage * GT_STAGE;
#pragma unroll
    for (int i = 0; i < 4; i++) {
        int tt  = t + 256 * i;
        int row = tt >> 3;
        int ch  = tt & 7;
        uint32_t soff = SWZ128(row * 128 + ch * 16);
        const __nv_bfloat16* ga = Ahi + (size_t)(m0 + row) * DM + k0 + ch * 8;
        CP_ASYNC16(base + soff,               ga);
        const __nv_bfloat16* gal = Alo + (size_t)(m0 + row) * DM + k0 + ch * 8;
        CP_ASYNC16(base + GT_TILE + soff,     gal);
        const __nv_bfloat16* gb = Bhi + (size_t)(n0 + row) * DM + k0 + ch * 8;
        CP_ASYNC16(base + 2*GT_TILE + soff,   gb);
        const __nv_bfloat16* gbl = Blo + (size_t)(n0 + row) * DM + k0 + ch * 8;
        CP_ASYNC16(base + 3*GT_TILE + soff,   gbl);
    }
    CP_COMMIT();
}

__global__ void __launch_bounds__(256)
gemm_hmma(const __nv_bfloat16* __restrict__ Ahi, const __nv_bfloat16* __restrict__ Alo,
          const __nv_bfloat16* __restrict__ Bhi, const __nv_bfloat16* __restrict__ Blo,
          float* __restrict__ out, int headsplit)
{
    extern __shared__ char smem[];
    const uint32_t sb = smem_u32(smem);
    const int t   = threadIdx.x;
    const int wid = t >> 5, lid = t & 31;
    const int wm  = wid & 3;        // 0..3 -> 32-row band
    const int wn  = wid >> 2;       // 0..1 -> 64-col band
    const int m0  = blockIdx.y * 128;
    const int n0  = blockIdx.x * 128;

    float acc[2][8][4];
#pragma unroll
    for (int a = 0; a < 2; a++)
#pragma unroll
        for (int b = 0; b < 8; b++)
#pragma unroll
            for (int c = 0; c < 4; c++) acc[a][b][c] = 0.0f;

    g_load_stage(sb, 0, Ahi, Alo, Bhi, Blo, m0, n0, 0,  t);
    g_load_stage(sb, 1, Ahi, Alo, Bhi, Blo, m0, n0, 64, t);

    for (int c = 0; c < NCHUNK; c++) {
        if (c < NCHUNK - 1) { CP_WAIT1(); } else { CP_WAIT0(); }
        __syncthreads();

        const uint32_t st = sb + (c & 1) * GT_STAGE;
#pragma unroll
        for (int ks = 0; ks < 4; ks++) {
            const int colb = ks * 32 + ((lid >> 4) << 4);   // byte col within row
            uint32_t ah[2][4], al[2][4];
#pragma unroll
            for (int mt = 0; mt < 2; mt++) {
                int row = wm * 32 + mt * 16 + (lid & 15);
                uint32_t off = SWZ128(row * 128 + colb);
                LDSM4(ah[mt][0], ah[mt][1], ah[mt][2], ah[mt][3], st + off);
                LDSM4(al[mt][0], al[mt][1], al[mt][2], al[mt][3], st + GT_TILE + off);
            }
            uint32_t bh[4][4], bl[4][4];
#pragma unroll
            for (int np = 0; np < 4; np++) {
                int row = wn * 64 + np * 16 + (lid & 15);
                uint32_t off = SWZ128(row * 128 + colb);
                LDSM4(bh[np][0], bh[np][1], bh[np][2], bh[np][3], st + 2*GT_TILE + off);
                LDSM4(bl[np][0], bl[np][1], bl[np][2], bl[np][3], st + 3*GT_TILE + off);
            }
#pragma unroll
            for (int mt = 0; mt < 2; mt++) {
#pragma unroll
                for (int np = 0; np < 4; np++) {
                    // n-tile 2*np (B regs 0,2) and 2*np+1 (B regs 1,3)
                    mma16816(acc[mt][2*np],   ah[mt], bh[np][0], bh[np][2]);
                    mma16816(acc[mt][2*np],   ah[mt], bl[np][0], bl[np][2]);
                    mma16816(acc[mt][2*np],   al[mt], bh[np][0], bh[np][2]);
                    mma16816(acc[mt][2*np+1], ah[mt], bh[np][1], bh[np][3]);
                    mma16816(acc[mt][2*np+1], ah[mt], bl[np][1], bl[np][3]);
                    mma16816(acc[mt][2*np+1], al[mt], bh[np][1], bh[np][3]);
                }
            }
        }
        __syncthreads();
        if (c + 2 < NCHUNK)
            g_load_stage(sb, c & 1, Ahi, Alo, Bhi, Blo, m0, n0, (c + 2) * 64, t);
    }

    // epilogue
#pragma unroll
    for (int mt = 0; mt < 2; mt++) {
#pragma unroll
        for (int nt = 0; nt < 8; nt++) {
            int row0 = m0 + wm * 32 + mt * 16 + (lid >> 2);
            int col  = n0 + wn * 64 + nt * 8 + (lid & 3) * 2;
#pragma unroll
            for (int half = 0; half < 2; half++) {
                int row = row0 + half * 8;
                float2 v;
                v.x = acc[mt][nt][half * 2 + 0];
                v.y = acc[mt][nt][half * 2 + 1];
                float* dst;
                if (headsplit) {
                    int bb = row >> 11, tt2 = row & 2047;
                    int h = col >> 6, dh = col & 63;
                    dst = &out[((((size_t)bb * NH + h) * SEQ) + tt2) * HD + dh];
                } else {
                    dst = &out[(size_t)row * DM + col];
                }
                *(float2*)dst = v;
            }
        }
    }
}

// ---------------------------------------------------------------------------
// Flash attention (fp32 SIMT). One CTA = (b,h) x 128 q-rows, 128 threads,
// 1 q-row/thread. Probs in regs; causal check only on diagonal tiles.
// ---------------------------------------------------------------------------
#define QT 128
#define KT 64
#define QPAD 65
#define ATTN_SMEM_FLOATS (QT*QPAD + KT*HD + KT*HD + KT)
#define ATTN_SMEM_BYTES  (ATTN_SMEM_FLOATS*4)

__global__ void __launch_bounds__(128)
attn_kernel(const float* __restrict__ qh, const float* __restrict__ kh,
            const float* __restrict__ vh, const float* __restrict__ amask,
            const int* __restrict__ mask_future, float* __restrict__ ctx)
{
    extern __shared__ float sm[];
    float* Qs  = sm;                         // [128][65]
    float* Kst = Qs  + QT*QPAD;              // [64][64]  (Kst[k][j])
    float* Vs  = Kst + KT*HD;                // [64][64]  (Vs[j][k])
    float* Ps  = Vs  + KT*HD;                // [64]

    const int bh = blockIdx.y;
    const int b  = bh >> 4;
    const int h  = bh & 15;
    const int qt = blockIdx.x;
    const int t  = threadIdx.x;
    const int gq = qt*QT + t;

    const float* Qbase = qh + (size_t)bh * SEQ * HD;
    const float* Kbase = kh + (size_t)bh * SEQ * HD;
    const float* Vbase = vh + (size_t)bh * SEQ * HD;

#pragma unroll
    for (int i = 0; i < 16; i++) {
        int f4  = t + 128*i;
        int row = f4 >> 4;
        int c4  = (f4 & 15) * 4;
        float4 v = *(const float4*)&Qbase[(size_t)(qt*QT + row)*HD + c4];
        Qs[row*QPAD + c4 + 0] = v.x;
        Qs[row*QPAD + c4 + 1] = v.y;
        Qs[row*QPAD + c4 + 2] = v.z;
        Qs[row*QPAD + c4 + 3] = v.w;
    }

    const int causal = mask_future[0] != 0;
    const int ntiles = causal ? (qt*QT + QT) / KT : SEQ / KT;
    const int nfull  = causal ? (qt*QT) / KT : ntiles;

    float m = -1e30f, l = 0.0f;
    float acc[HD];
#pragma unroll
    for (int k = 0; k < HD; k++) acc[k] = 0.0f;

    for (int kt = 0; kt < ntiles; kt++) {
        __syncthreads();
        const float* Kb = Kbase + (size_t)(kt*KT)*HD;
        const float* Vb = Vbase + (size_t)(kt*KT)*HD;
#pragma unroll
        for (int i = 0; i < 8; i++) {
            int f4  = t + 128*i;
            int row = f4 >> 4;
            int c4  = (f4 & 15) * 4;
            float4 kv = *(const float4*)&Kb[(size_t)row*HD + c4];
            Kst[(c4+0)*KT + row] = kv.x;
            Kst[(c4+1)*KT + row] = kv.y;
            Kst[(c4+2)*KT + row] = kv.z;
            Kst[(c4+3)*KT + row] = kv.w;
            float4 vv = *(const float4*)&Vb[(size_t)row*HD + c4];
            *(float4*)&Vs[row*HD + c4] = vv;
        }
        if (t < KT) Ps[t] = amask[(size_t)b*SEQ + kt*KT + t];
        __syncthreads();

        float s[KT];
#pragma unroll
        for (int j = 0; j < KT; j++) s[j] = 0.0f;
#pragma unroll 4
        for (int k = 0; k < HD; k++) {
            float qv = Qs[t*QPAD + k];
            const float4* Kr = (const float4*)&Kst[k*KT];
#pragma unroll
            for (int j4 = 0; j4 < 16; j4++) {
                float4 kk = Kr[j4];
                s[j4*4+0] += qv * kk.x;
                s[j4*4+1] += qv * kk.y;
                s[j4*4+2] += qv * kk.z;
                s[j4*4+3] += qv * kk.w;
            }
        }

        float tmax = -1e30f;
        if (kt < nfull) {
#pragma unroll
            for (int j = 0; j < KT; j++) {
                float sv = s[j] * 0.125f;
                if (Ps[j] == 0.0f) sv = NEGBIAS;
                s[j] = sv;
                tmax = fmaxf(tmax, sv);
            }
        } else {
#pragma unroll
            for (int j = 0; j < KT; j++) {
                float sv = s[j] * 0.125f;
                int gk = kt*KT + j;
                if (gk > gq) sv += NEGBIAS;
                if (Ps[j] == 0.0f) sv = NEGBIAS;
                s[j] = sv;
                tmax = fmaxf(tmax, sv);
            }
        }
        float mn   = fmaxf(m, tmax);
        float corr = __expf(m - mn);
        l *= corr;
#pragma unroll
        for (int j = 0; j < KT; j++) {
            float p = __expf(s[j] - mn);
            l += p;
            s[j] = p;
        }
        m = mn;
#pragma unroll
        for (int k = 0; k < HD; k++) acc[k] *= corr;

#pragma unroll 2
        for (int j = 0; j < KT; j++) {
            float p = s[j];
            const float4* Vr = (const float4*)&Vs[j*HD];
#pragma unroll
            for (int k4 = 0; k4 < 16; k4++) {
                float4 vv = Vr[k4];
                acc[k4*4+0] += p * vv.x;
                acc[k4*4+1] += p * vv.y;
                acc[k4*4+2] += p * vv.z;
                acc[k4*4+3] += p * vv.w;
            }
        }
    }

    float rl = 1.0f / l;
    float* Cb = g_ctx + ((size_t)b*SEQ + gq)*DM + h*HD;
#pragma unroll
    for (int k4 = 0; k4 < 16; k4++) {
        float4 o;
        o.x = acc[k4*4+0] * rl;
        o.y = acc[k4*4+1] * rl;
        o.z = acc[k4*4+2] * rl;
        o.w = acc[k4*4+3] * rl;
        *(float4*)&Cb[k4*4] = o;
    }
}

// ---------------------------------------------------------------------------
extern "C" void kernel_launch(void* const* d_in, const int* in_sizes, int n_in,
                              void* d_out, int out_size)
{
    const float* q  = (const float*)d_in[0];
    const float* k  = (const float*)d_in[1];
    const float* v  = (const float*)d_in[2];
    const float* am = (const float*)d_in[3];
    const float* Wq = (const float*)d_in[4];
    const float* Wk = (const float*)d_in[5];
    const float* Wv = (const float*)d_in[6];
    const float* Wo = (const float*)d_in[7];
    const int*   mf = (const int*)  d_in[8];
    float* out = (float*)d_out;

    float *qh, *kh, *vh, *ctx;
    __nv_bfloat16 *ahi, *alo, *whi, *wlo;
    cudaGetSymbolAddress((void**)&qh,  g_qh);
    cudaGetSymbolAddress((void**)&kh,  g_kh);
    cudaGetSymbolAddress((void**)&vh,  g_vh);
    cudaGetSymbolAddress((void**)&ctx, g_ctx);
    cudaGetSymbolAddress((void**)&ahi, g_ahi);
    cudaGetSymbolAddress((void**)&alo, g_alo);
    cudaGetSymbolAddress((void**)&whi, g_whi);
    cudaGetSymbolAddress((void**)&wlo, g_wlo);

    static bool attr_set = false;
    if (!attr_set) {
        cudaFuncSetAttribute(attn_kernel,
                             cudaFuncAttributeMaxDynamicSharedMemorySize,
                             ATTN_SMEM_BYTES);
        cudaFuncSetAttribute(gemm_hmma,
                             cudaFuncAttributeMaxDynamicSharedMemorySize,
                             GSMEM_BYTES);
        attr_set = true;
    }

    const int nX4 = MROWS * DM / 4;      // activations, float4 count
    const int nW4 = DM * DM / 4;         // weights
    dim3 ggrid(DM/128, MROWS/128);       // (8, 64)

    // Q projection
    split_bf16<<<(nX4+255)/256, 256>>>((const float4*)q,  (uint2*)ahi, (uint2*)alo, nX4);
    split_bf16<<<(nW4+255)/256, 256>>>((const float4*)Wq, (uint2*)whi, (uint2*)wlo, nW4);
    gemm_hmma<<<ggrid, 256, GSMEM_BYTES>>>(ahi, alo, whi, wlo, qh, 1);
    // K projection
    split_bf16<<<(nX4+255)/256, 256>>>((const float4*)k,  (uint2*)ahi, (uint2*)alo, nX4);
    split_bf16<<<(nW4+255)/256, 256>>>((const float4*)Wk, (uint2*)whi, (uint2*)wlo, nW4);
    gemm_hmma<<<ggrid, 256, GSMEM_BYTES>>>(ahi, alo, whi, wlo, kh, 1);
    // V projection
    split_bf16<<<(nX4+255)/256, 256>>>((const float4*)v,  (uint2*)ahi, (uint2*)alo, nX4);
    split_bf16<<<(nW4+255)/256, 256>>>((const float4*)Wv, (uint2*)whi, (uint2*)wlo, nW4);
    gemm_hmma<<<ggrid, 256, GSMEM_BYTES>>>(ahi, alo, whi, wlo, vh, 1);

    // attention
    dim3 agrid(SEQ/QT, BATCH*NH);        // (16, 64)
    attn_kernel<<<agrid, 128, ATTN_SMEM_BYTES>>>(qh, kh, vh, am, mf, ctx);

    // output projection
    split_bf16<<<(nX4+255)/256, 256>>>((const float4*)ctx, (uint2*)ahi, (uint2*)alo, nX4);
    split_bf16<<<(nW4+255)/256, 256>>>((const float4*)Wo,  (uint2*)whi, (uint2*)wlo, nW4);
    gemm_hmma<<<ggrid, 256, GSMEM_BYTES>>>(ahi, alo, whi, wlo, out, 0);
}

// round 6
// speedup vs baseline: 3.0744x; 2.3906x over previous
#include <cuda_runtime.h>
#include <cuda_bf16.h>
#include <cstdint>

// Problem constants
#define BATCH 4
#define SEQ   2048
#define DM    1024
#define NH    16
#define HD    64
#define MROWS (BATCH*SEQ)          // 8192
#define NEGBIAS (-10000.0f)

// Scratch (no allocation allowed)
// bf16 hi/lo head-split projections [bh][t][hd]
__device__ __nv_bfloat16 g_qhi[BATCH*NH*SEQ*HD];
__device__ __nv_bfloat16 g_qlo[BATCH*NH*SEQ*HD];
__device__ __nv_bfloat16 g_khi[BATCH*NH*SEQ*HD];
__device__ __nv_bfloat16 g_klo[BATCH*NH*SEQ*HD];
__device__ __nv_bfloat16 g_vhi[BATCH*NH*SEQ*HD];
__device__ __nv_bfloat16 g_vlo[BATCH*NH*SEQ*HD];
// activation / weight split buffers for GEMMs (attention writes ctx into a*)
__device__ __nv_bfloat16 g_ahi[MROWS*DM];
__device__ __nv_bfloat16 g_alo[MROWS*DM];
__device__ __nv_bfloat16 g_whi[DM*DM];
__device__ __nv_bfloat16 g_wlo[DM*DM];

// ---------------------------------------------------------------------------
// helpers
// ---------------------------------------------------------------------------
__device__ __forceinline__ uint32_t smem_u32(const void* p) {
    uint32_t a;
    asm("{ .reg .u64 t; cvta.to.shared.u64 t, %1; cvt.u32.u64 %0, t; }" : "=r"(a) : "l"(p));
    return a;
}
#define SWZ128(o) ((uint32_t)(o) ^ ((((uint32_t)(o)) >> 3) & 0x70))

#define CP_ASYNC16(saddr, gptr) \
    asm volatile("cp.async.cg.shared.global [%0], [%1], 16;" :: "r"(saddr), "l"(gptr) : "memory")
#define CP_ASYNC4(saddr, gptr) \
    asm volatile("cp.async.ca.shared.global [%0], [%1], 4;" :: "r"(saddr), "l"(gptr) : "memory")
#define CP_COMMIT() asm volatile("cp.async.commit_group;" ::: "memory")
#define CP_WAIT1()  asm volatile("cp.async.wait_group 1;" ::: "memory")
#define CP_WAIT0()  asm volatile("cp.async.wait_group 0;" ::: "memory")

#define LDSM4(R0,R1,R2,R3,ADDR) \
    asm volatile("ldmatrix.sync.aligned.m8n8.x4.shared.b16 {%0,%1,%2,%3}, [%4];" \
        : "=r"(R0), "=r"(R1), "=r"(R2), "=r"(R3) : "r"(ADDR))
#define LDSM4T(R0,R1,R2,R3,ADDR) \
    asm volatile("ldmatrix.sync.aligned.m8n8.x4.trans.shared.b16 {%0,%1,%2,%3}, [%4];" \
        : "=r"(R0), "=r"(R1), "=r"(R2), "=r"(R3) : "r"(ADDR))

__device__ __forceinline__ void mma16816(float* c, const uint32_t* a,
                                         uint32_t b0, uint32_t b1) {
    asm volatile(
        "mma.sync.aligned.m16n8k16.row.col.f32.bf16.bf16.f32 "
        "{%0,%1,%2,%3}, {%4,%5,%6,%7}, {%8,%9}, {%0,%1,%2,%3};"
        : "+f"(c[0]), "+f"(c[1]), "+f"(c[2]), "+f"(c[3])
        : "r"(a[0]), "r"(a[1]), "r"(a[2]), "r"(a[3]), "r"(b0), "r"(b1));
}

__device__ __forceinline__ uint32_t pack_bf2(float a, float b) {
    __nv_bfloat162 t = __floats2bfloat162_rn(a, b);
    return *(uint32_t*)&t;
}
__device__ __forceinline__ void split1(float v, float& hi_f, uint16_t& hi, uint16_t& lo) {
    __nv_bfloat16 bh = __float2bfloat16(v);
    hi_f = __bfloat162float(bh);
    hi = __bfloat16_as_ushort(bh);
    lo = __bfloat16_as_ushort(__float2bfloat16(v - hi_f));
}

// ---------------------------------------------------------------------------
// split kernel: fp32 -> bf16 hi + bf16 residual lo
// ---------------------------------------------------------------------------
__global__ void __launch_bounds__(256)
split_bf16(const float4* __restrict__ src, uint2* __restrict__ hi,
           uint2* __restrict__ lo, int n4)
{
    int i = blockIdx.x * 256 + threadIdx.x;
    if (i >= n4) return;
    float4 v = src[i];
    float f[4] = {v.x, v.y, v.z, v.w};
    uint32_t h[4], l[4];
#pragma unroll
    for (int j = 0; j < 4; j++) {
        float hf; uint16_t hb, lb;
        split1(f[j], hf, hb, lb);
        h[j] = hb; l[j] = lb;
    }
    hi[i] = make_uint2(h[0] | (h[1] << 16), h[2] | (h[3] << 16));
    lo[i] = make_uint2(l[0] | (l[1] << 16), l[2] | (l[3] << 16));
}

// ---------------------------------------------------------------------------
// HMMA GEMM: out[m,n] = sum_k X[m,k]*W[n,k], X/W pre-split bf16 hi/lo.
// headsplit=1: write bf16 hi/lo to (ohi, olo) in [bh][t][hd] layout.
// headsplit=0: write f32 to outf, [m][n] row-major.
// ---------------------------------------------------------------------------
#define GT_TILE  16384
#define GT_STAGE (4*GT_TILE)
#define GSMEM_BYTES (2*GT_STAGE)   // 128 KB
#define NCHUNK 16                  // K=1024 / 64

__device__ __forceinline__ void g_load_stage(
    uint32_t sb, int stage,
    const __nv_bfloat16* __restrict__ Ahi, const __nv_bfloat16* __restrict__ Alo,
    const __nv_bfloat16* __restrict__ Bhi, const __nv_bfloat16* __restrict__ Blo,
    int m0, int n0, int k0, int t)
{
    const uint32_t base = sb + stage * GT_STAGE;
#pragma unroll
    for (int i = 0; i < 4; i++) {
        int tt  = t + 256 * i;
        int row = tt >> 3;
        int ch  = tt & 7;
        uint32_t soff = SWZ128(row * 128 + ch * 16);
        CP_ASYNC16(base + soff,             Ahi + (size_t)(m0 + row) * DM + k0 + ch * 8);
        CP_ASYNC16(base + GT_TILE + soff,   Alo + (size_t)(m0 + row) * DM + k0 + ch * 8);
        CP_ASYNC16(base + 2*GT_TILE + soff, Bhi + (size_t)(n0 + row) * DM + k0 + ch * 8);
        CP_ASYNC16(base + 3*GT_TILE + soff, Blo + (size_t)(n0 + row) * DM + k0 + ch * 8);
    }
    CP_COMMIT();
}

__global__ void __launch_bounds__(256)
gemm_hmma(const __nv_bfloat16* __restrict__ Ahi, const __nv_bfloat16* __restrict__ Alo,
          const __nv_bfloat16* __restrict__ Bhi, const __nv_bfloat16* __restrict__ Blo,
          __nv_bfloat16* __restrict__ ohi, __nv_bfloat16* __restrict__ olo,
          float* __restrict__ outf, int headsplit)
{
    extern __shared__ char smem[];
    const uint32_t sb = smem_u32(smem);
    const int t   = threadIdx.x;
    const int wid = t >> 5, lid = t & 31;
    const int wm  = wid & 3;
    const int wn  = wid >> 2;
    const int m0  = blockIdx.y * 128;
    const int n0  = blockIdx.x * 128;

    float acc[2][8][4];
#pragma unroll
    for (int a = 0; a < 2; a++)
#pragma unroll
        for (int b = 0; b < 8; b++)
#pragma unroll
            for (int c = 0; c < 4; c++) acc[a][b][c] = 0.0f;

    g_load_stage(sb, 0, Ahi, Alo, Bhi, Blo, m0, n0, 0,  t);
    g_load_stage(sb, 1, Ahi, Alo, Bhi, Blo, m0, n0, 64, t);

    for (int c = 0; c < NCHUNK; c++) {
        if (c < NCHUNK - 1) { CP_WAIT1(); } else { CP_WAIT0(); }
        __syncthreads();

        const uint32_t st = sb + (c & 1) * GT_STAGE;
#pragma unroll
        for (int ks = 0; ks < 4; ks++) {
            const int colb = ks * 32 + ((lid >> 4) << 4);
            uint32_t ah[2][4], al[2][4];
#pragma unroll
            for (int mt = 0; mt < 2; mt++) {
                int row = wm * 32 + mt * 16 + (lid & 15);
                uint32_t off = SWZ128(row * 128 + colb);
                LDSM4(ah[mt][0], ah[mt][1], ah[mt][2], ah[mt][3], st + off);
                LDSM4(al[mt][0], al[mt][1], al[mt][2], al[mt][3], st + GT_TILE + off);
            }
            uint32_t bh[4][4], bl[4][4];
#pragma unroll
            for (int np = 0; np < 4; np++) {
                int row = wn * 64 + np * 16 + (lid & 15);
                uint32_t off = SWZ128(row * 128 + colb);
                LDSM4(bh[np][0], bh[np][1], bh[np][2], bh[np][3], st + 2*GT_TILE + off);
                LDSM4(bl[np][0], bl[np][1], bl[np][2], bl[np][3], st + 3*GT_TILE + off);
            }
#pragma unroll
            for (int mt = 0; mt < 2; mt++) {
#pragma unroll
                for (int np = 0; np < 4; np++) {
                    mma16816(acc[mt][2*np],   ah[mt], bh[np][0], bh[np][2]);
                    mma16816(acc[mt][2*np],   ah[mt], bl[np][0], bl[np][2]);
                    mma16816(acc[mt][2*np],   al[mt], bh[np][0], bh[np][2]);
                    mma16816(acc[mt][2*np+1], ah[mt], bh[np][1], bh[np][3]);
                    mma16816(acc[mt][2*np+1], ah[mt], bl[np][1], bl[np][3]);
                    mma16816(acc[mt][2*np+1], al[mt], bh[np][1], bh[np][3]);
                }
            }
        }
        __syncthreads();
        if (c + 2 < NCHUNK)
            g_load_stage(sb, c & 1, Ahi, Alo, Bhi, Blo, m0, n0, (c + 2) * 64, t);
    }

    // epilogue
#pragma unroll
    for (int mt = 0; mt < 2; mt++) {
#pragma unroll
        for (int nt = 0; nt < 8; nt++) {
            int row0 = m0 + wm * 32 + mt * 16 + (lid >> 2);
            int col  = n0 + wn * 64 + nt * 8 + (lid & 3) * 2;
#pragma unroll
            for (int half = 0; half < 2; half++) {
                int row = row0 + half * 8;
                float vx = acc[mt][nt][half * 2 + 0];
                float vy = acc[mt][nt][half * 2 + 1];
                if (headsplit) {
                    int bb = row >> 11, tt2 = row & 2047;
                    int h = col >> 6, dh = col & 63;
                    size_t base = ((((size_t)bb * NH + h) * SEQ) + tt2) * HD + dh;
                    float hfx, hfy; uint16_t hx, lx, hy, ly;
                    split1(vx, hfx, hx, lx);
                    split1(vy, hfy, hy, ly);
                    *(uint32_t*)&ohi[base] = (uint32_t)hx | ((uint32_t)hy << 16);
                    *(uint32_t*)&olo[base] = (uint32_t)lx | ((uint32_t)ly << 16);
                } else {
                    float2 v2; v2.x = vx; v2.y = vy;
                    *(float2*)&outf[(size_t)row * DM + col] = v2;
                }
            }
        }
    }
}

// ---------------------------------------------------------------------------
// HMMA flash attention. CTA = (b,h) x 128 q rows, 8 warps x 16 rows.
// K-tile 64, 2-stage cp.async pipeline. Q/K/P/V all bf16 hi/lo (3-product).
// smem: Qhi 16K | Qlo 16K | stage s (32K): Khi 8K Klo 8K Vhi 8K Vlo 8K |
//       mask: 2 stages x 64 floats
// ---------------------------------------------------------------------------
#define AT_KT   64
#define AT_STG0 32768
#define AT_STGB 32768
#define AT_MSK  (AT_STG0 + 2*AT_STGB)      // 98304
#define ATTN_SMEM_BYTES (AT_MSK + 512)

__device__ __forceinline__ void a_load_stage(
    uint32_t sb, int stage,
    const __nv_bfloat16* Khi, const __nv_bfloat16* Klo,
    const __nv_bfloat16* Vhi, const __nv_bfloat16* Vlo,
    const float* amaskb, int kt0, int t)
{
    const uint32_t base = sb + AT_STG0 + stage * AT_STGB;
#pragma unroll
    for (int i = 0; i < 8; i++) {
        int chunk = t + 256 * i;            // 0..2047
        int tsel  = chunk >> 9;             // 0..3
        int c     = chunk & 511;
        int row   = c >> 3;
        int ch    = c & 7;
        uint32_t soff = (uint32_t)tsel * 8192 + SWZ128(row * 128 + ch * 16);
        const __nv_bfloat16* src =
            (tsel == 0) ? Khi : (tsel == 1) ? Klo : (tsel == 2) ? Vhi : Vlo;
        CP_ASYNC16(base + soff, src + (size_t)(kt0 + row) * HD + ch * 8);
    }
    if (t < AT_KT)
        CP_ASYNC4(sb + AT_MSK + stage * 256 + t * 4, amaskb + kt0 + t);
    CP_COMMIT();
}

__global__ void __launch_bounds__(256)
attn_hmma(const float* __restrict__ amask, const int* __restrict__ mask_future,
          __nv_bfloat16* __restrict__ chi, __nv_bfloat16* __restrict__ clo)
{
    extern __shared__ char smem[];
    const uint32_t sb = smem_u32(smem);
    const int t   = threadIdx.x;
    const int wid = t >> 5, lid = t & 31;
    const int bh  = blockIdx.y;
    const int b   = bh >> 4;
    const int h   = bh & 15;
    const int qt  = blockIdx.x;
    const int m0w = wid * 16;               // warp's q-row base within tile

    const size_t bhoff = (size_t)bh * SEQ * HD;
    const __nv_bfloat16* Qhi = g_qhi + bhoff;
    const __nv_bfloat16* Qlo = g_qlo + bhoff;
    const __nv_bfloat16* Khi = g_khi + bhoff;
    const __nv_bfloat16* Klo = g_klo + bhoff;
    const __nv_bfloat16* Vhi = g_vhi + bhoff;
    const __nv_bfloat16* Vlo = g_vlo + bhoff;
    const float* amaskb = amask + (size_t)b * SEQ;

    // load Q hi/lo (128 rows x 64 cols bf16, SW128) + stage 0, one group
#pragma unroll
    for (int i = 0; i < 4; i++) {
        int chunk = t + 256 * i;            // 0..1023
        int row   = chunk >> 3;
        int ch    = chunk & 7;
        uint32_t soff = SWZ128(row * 128 + ch * 16);
        CP_ASYNC16(sb + soff,         Qhi + (size_t)(qt*128 + row) * HD + ch * 8);
        CP_ASYNC16(sb + 16384 + soff, Qlo + (size_t)(qt*128 + row) * HD + ch * 8);
    }
    const int causal = mask_future[0] != 0;
    const int ntiles = causal ? (qt * 2 + 2) : (SEQ / AT_KT);
    const int nfull  = causal ? (qt * 2)     : ntiles;

    a_load_stage(sb, 0, Khi, Klo, Vhi, Vlo, amaskb, 0, t);           // group 0 (w/ Q)
    a_load_stage(sb, 1, Khi, Klo, Vhi, Vlo, amaskb, AT_KT, t);       // group 1

    const int r1 = lid >> 2;                // row within m16 (0..7); r2 = r1+8
    const int gq1 = qt*128 + m0w + r1;
    const int gq2 = gq1 + 8;
    const int cq  = (lid & 3) * 2;          // col pair base within n8

    float m1 = -1e30f, m2 = -1e30f, l1 = 0.0f, l2 = 0.0f;
    float O[8][4];
#pragma unroll
    for (int i = 0; i < 8; i++)
#pragma unroll
        for (int j = 0; j < 4; j++) O[i][j] = 0.0f;

    for (int kt = 0; kt < ntiles; kt++) {
        if (kt < ntiles - 1) { CP_WAIT1(); } else { CP_WAIT0(); }
        __syncthreads();

        const uint32_t st  = sb + AT_STG0 + (kt & 1) * AT_STGB;
        const uint32_t msk = sb + AT_MSK + (kt & 1) * 256;

        // ---- S = Q K^T (hi/lo 3-product) ----
        float S[8][4];
#pragma unroll
        for (int i = 0; i < 8; i++)
#pragma unroll
            for (int j = 0; j < 4; j++) S[i][j] = 0.0f;

#pragma unroll
        for (int k16 = 0; k16 < 4; k16++) {
            const int colb = k16 * 32 + (lid >> 4) * 16;
            uint32_t qh_[4], ql_[4];
            {
                int row = m0w + (lid & 15);
                uint32_t off = SWZ128(row * 128 + colb);
                LDSM4(qh_[0], qh_[1], qh_[2], qh_[3], sb + off);
                LDSM4(ql_[0], ql_[1], ql_[2], ql_[3], sb + 16384 + off);
            }
#pragma unroll
            for (int np = 0; np < 4; np++) {
                int row = np * 16 + (lid & 15);
                uint32_t off = SWZ128(row * 128 + colb);
                uint32_t kh_[4], kl_[4];
                LDSM4(kh_[0], kh_[1], kh_[2], kh_[3], st + off);
                LDSM4(kl_[0], kl_[1], kl_[2], kl_[3], st + 8192 + off);
                mma16816(S[2*np],   qh_, kh_[0], kh_[2]);
                mma16816(S[2*np],   qh_, kl_[0], kl_[2]);
                mma16816(S[2*np],   ql_, kh_[0], kh_[2]);
                mma16816(S[2*np+1], qh_, kh_[1], kh_[3]);
                mma16816(S[2*np+1], qh_, kl_[1], kl_[3]);
                mma16816(S[2*np+1], ql_, kh_[1], kh_[3]);
            }
        }

        // ---- scale + masks ----
        const int diag = (kt >= nfull);
#pragma unroll
        for (int nt = 0; nt < 8; nt++) {
            int jl0 = nt * 8 + cq;
            float p0, p1;
            asm("ld.shared.f32 %0, [%1];" : "=f"(p0) : "r"(msk + jl0 * 4));
            asm("ld.shared.f32 %0, [%1];" : "=f"(p1) : "r"(msk + jl0 * 4 + 4));
            int gk0 = kt * AT_KT + jl0;
#pragma unroll
            for (int c = 0; c < 4; c++) {
                float sv = S[nt][c] * 0.125f;
                int gk = gk0 + (c & 1);
                int gq = (c < 2) ? gq1 : gq2;
                if (diag && gk > gq) sv += NEGBIAS;
                float pm = (c & 1) ? p1 : p0;
                if (pm == 0.0f) sv = NEGBIAS;
                S[nt][c] = sv;
            }
        }

        // ---- online softmax ----
        float t1 = -1e30f, t2 = -1e30f;
#pragma unroll
        for (int nt = 0; nt < 8; nt++) {
            t1 = fmaxf(t1, fmaxf(S[nt][0], S[nt][1]));
            t2 = fmaxf(t2, fmaxf(S[nt][2], S[nt][3]));
        }
        t1 = fmaxf(t1, __shfl_xor_sync(0xffffffffu, t1, 1));
        t1 = fmaxf(t1, __shfl_xor_sync(0xffffffffu, t1, 2));
        t2 = fmaxf(t2, __shfl_xor_sync(0xffffffffu, t2, 1));
        t2 = fmaxf(t2, __shfl_xor_sync(0xffffffffu, t2, 2));
        float mn1 = fmaxf(m1, t1), mn2 = fmaxf(m2, t2);
        float corr1 = __expf(m1 - mn1), corr2 = __expf(m2 - mn2);
        m1 = mn1; m2 = mn2;
        l1 *= corr1; l2 *= corr2;

        uint32_t phi[4][4], plo[4][4];       // A-frags per k16 chunk of kt
#pragma unroll
        for (int nt2 = 0; nt2 < 4; nt2++) {  // pairs of n8 tiles -> k16
#pragma unroll
            for (int half = 0; half < 2; half++) {
                int nt = 2*nt2 + half;
                float e0 = __expf(S[nt][0] - mn1);
                float e1 = __expf(S[nt][1] - mn1);
                float e2 = __expf(S[nt][2] - mn2);
                float e3 = __expf(S[nt][3] - mn2);
                l1 += e0 + e1; l2 += e2 + e3;
                float h0f, h1f, h2f, h3f; uint16_t hh0, ll0, hh1, ll1, hh2, ll2, hh3, ll3;
                split1(e0, h0f, hh0, ll0); split1(e1, h1f, hh1, ll1);
                split1(e2, h2f, hh2, ll2); split1(e3, h3f, hh3, ll3);
                phi[nt2][2*half]   = (uint32_t)hh0 | ((uint32_t)hh1 << 16);
                phi[nt2][2*half+1] = (uint32_t)hh2 | ((uint32_t)hh3 << 16);
                plo[nt2][2*half]   = (uint32_t)ll0 | ((uint32_t)ll1 << 16);
                plo[nt2][2*half+1] = (uint32_t)ll2 | ((uint32_t)ll3 << 16);
            }
        }
        // A-frag ordering fix: regs must be (r1,k0:8),(r2,k0:8),(r1,k8:16),(r2,k8:16)
        // built above as: half0 -> regs {0:(r1),1:(r2)}, half1 -> regs {2:(r1),3:(r2)}  ✓

        // rescale O
#pragma unroll
        for (int i = 0; i < 8; i++) {
            O[i][0] *= corr1; O[i][1] *= corr1;
            O[i][2] *= corr2; O[i][3] *= corr2;
        }

        // ---- O += P V (hi/lo 3-product) ----
        const uint32_t vbase_hi = st + 16384, vbase_lo = st + 24576;
#pragma unroll
        for (int hdb = 0; hdb < 4; hdb++) {
#pragma unroll
            for (int k16 = 0; k16 < 4; k16++) {
                int row  = k16 * 16 + (lid & 7) + ((lid >> 3) & 1) * 8;
                int colb = hdb * 32 + (lid >> 4) * 16;
                uint32_t off = SWZ128(row * 128 + colb);
                uint32_t vh_[4], vl_[4];
                LDSM4T(vh_[0], vh_[1], vh_[2], vh_[3], vbase_hi + off);
                LDSM4T(vl_[0], vl_[1], vl_[2], vl_[3], vbase_lo + off);
                mma16816(O[2*hdb],   phi[k16], vh_[0], vh_[1]);
                mma16816(O[2*hdb],   phi[k16], vl_[0], vl_[1]);
                mma16816(O[2*hdb],   plo[k16], vh_[0], vh_[1]);
                mma16816(O[2*hdb+1], phi[k16], vh_[2], vh_[3]);
                mma16816(O[2*hdb+1], phi[k16], vl_[2], vl_[3]);
                mma16816(O[2*hdb+1], plo[k16], vh_[2], vh_[3]);
            }
        }

        __syncthreads();
        if (kt + 2 < ntiles)
            a_load_stage(sb, kt & 1, Khi, Klo, Vhi, Vlo, amaskb, (kt + 2) * AT_KT, t);
    }

    // finalize l across quad
    l1 += __shfl_xor_sync(0xffffffffu, l1, 1);
    l1 += __shfl_xor_sync(0xffffffffu, l1, 2);
    l2 += __shfl_xor_sync(0xffffffffu, l2, 1);
    l2 += __shfl_xor_sync(0xffffffffu, l2, 2);
    float rl1 = 1.0f / l1, rl2 = 1.0f / l2;

    // write ctx hi/lo into activation buffers [b*T+t][h*64+hd]
    const size_t rowb1 = ((size_t)b * SEQ + gq1) * DM + h * HD;
    const size_t rowb2 = ((size_t)b * SEQ + gq2) * DM + h * HD;
#pragma unroll
    for (int nt = 0; nt < 8; nt++) {
        int col = nt * 8 + cq;
        float v0 = O[nt][0] * rl1, v1 = O[nt][1] * rl1;
        float v2 = O[nt][2] * rl2, v3 = O[nt][3] * rl2;
        float hf; uint16_t h0, l0, h1b, l1b, h2, l2b, h3, l3;
        split1(v0, hf, h0, l0); split1(v1, hf, h1b, l1b);
        split1(v2, hf, h2, l2b); split1(v3, hf, h3, l3);
        *(uint32_t*)&chi[rowb1 + col] = (uint32_t)h0 | ((uint32_t)h1b << 16);
        *(uint32_t*)&clo[rowb1 + col] = (uint32_t)l0 | ((uint32_t)l1b << 16);
        *(uint32_t*)&chi[rowb2 + col] = (uint32_t)h2 | ((uint32_t)h3 << 16);
        *(uint32_t*)&clo[rowb2 + col] = (uint32_t)l2b | ((uint32_t)l3 << 16);
    }
}

// ---------------------------------------------------------------------------
extern "C" void kernel_launch(void* const* d_in, const int* in_sizes, int n_in,
                              void* d_out, int out_size)
{
    const float* q  = (const float*)d_in[0];
    const float* k  = (const float*)d_in[1];
    const float* v  = (const float*)d_in[2];
    const float* am = (const float*)d_in[3];
    const float* Wq = (const float*)d_in[4];
    const float* Wk = (const float*)d_in[5];
    const float* Wv = (const float*)d_in[6];
    const float* Wo = (const float*)d_in[7];
    const int*   mf = (const int*)  d_in[8];
    float* out = (float*)d_out;

    __nv_bfloat16 *qhi, *qlo, *khi, *klo, *vhi, *vlo, *ahi, *alo, *whi, *wlo;
    cudaGetSymbolAddress((void**)&qhi, g_qhi);
    cudaGetSymbolAddress((void**)&qlo, g_qlo);
    cudaGetSymbolAddress((void**)&khi, g_khi);
    cudaGetSymbolAddress((void**)&klo, g_klo);
    cudaGetSymbolAddress((void**)&vhi, g_vhi);
    cudaGetSymbolAddress((void**)&vlo, g_vlo);
    cudaGetSymbolAddress((void**)&ahi, g_ahi);
    cudaGetSymbolAddress((void**)&alo, g_alo);
    cudaGetSymbolAddress((void**)&whi, g_whi);
    cudaGetSymbolAddress((void**)&wlo, g_wlo);

    static bool attr_set = false;
    if (!attr_set) {
        cudaFuncSetAttribute(gemm_hmma,
                             cudaFuncAttributeMaxDynamicSharedMemorySize, GSMEM_BYTES);
        cudaFuncSetAttribute(attn_hmma,
                             cudaFuncAttributeMaxDynamicSharedMemorySize, ATTN_SMEM_BYTES);
        attr_set = true;
    }

    const int nX4 = MROWS * DM / 4;
    const int nW4 = DM * DM / 4;
    dim3 ggrid(DM/128, MROWS/128);       // (8, 64)

    split_bf16<<<(nX4+255)/256, 256>>>((const float4*)q,  (uint2*)ahi, (uint2*)alo, nX4);
    split_bf16<<<(nW4+255)/256, 256>>>((const float4*)Wq, (uint2*)whi, (uint2*)wlo, nW4);
    gemm_hmma<<<ggrid, 256, GSMEM_BYTES>>>(ahi, alo, whi, wlo, qhi, qlo, nullptr, 1);

    split_bf16<<<(nX4+255)/256, 256>>>((const float4*)k,  (uint2*)ahi, (uint2*)alo, nX4);
    split_bf16<<<(nW4+255)/256, 256>>>((const float4*)Wk, (uint2*)whi, (uint2*)wlo, nW4);
    gemm_hmma<<<ggrid, 256, GSMEM_BYTES>>>(ahi, alo, whi, wlo, khi, klo, nullptr, 1);

    split_bf16<<<(nX4+255)/256, 256>>>((const float4*)v,  (uint2*)ahi, (uint2*)alo, nX4);
    split_bf16<<<(nW4+255)/256, 256>>>((const float4*)Wv, (uint2*)whi, (uint2*)wlo, nW4);
    gemm_hmma<<<ggrid, 256, GSMEM_BYTES>>>(ahi, alo, whi, wlo, vhi, vlo, nullptr, 1);

    // attention: writes ctx hi/lo straight into (ahi, alo)
    dim3 agrid(SEQ/128, BATCH*NH);       // (16, 64)
    attn_hmma<<<agrid, 256, ATTN_SMEM_BYTES>>>(am, mf, ahi, alo);

    split_bf16<<<(nW4+255)/256, 256>>>((const float4*)Wo, (uint2*)whi, (uint2*)wlo, nW4);
    gemm_hmma<<<ggrid, 256, GSMEM_BYTES>>>(ahi, alo, whi, wlo, nullptr, nullptr, out, 0);
}